// round 12
// baseline (speedup 1.0000x reference)
#include <cuda_runtime.h>
#include <cuda_bf16.h>
#include <math.h>

#define H_DIM 768
#define S_LEN 512
#define B_SZ 128
#define F4_PER_ROW (H_DIM / 4)      // 192
#define CHUNKS (H_DIM / 128)        // 6
#define RQ 4
#define QPW 4                       // 16 rows/warp
#define THREADS 256                 // 8 warps -> 128 rows/block
#define BLOCKS 512                  // <= 608 slots: ONE resident wave
#define QUAD_F4 (RQ * F4_PER_ROW)   // 768 float4 per quad
#define LN2F 0.6931471805599453f
#define FULLM 0xffffffffu

// Per-block CRF partials (block = quarter batch)
__device__ float g_sm_[BLOCKS][9];
__device__ float g_sls[BLOCKS];
__device__ float g_sg[BLOCKS];
__device__ float g_part[B_SZ];
__device__ unsigned int g_cnt[B_SZ];   // zero-init; combiner resets its slot
__device__ unsigned int g_done;        // zero-init; finalizer resets

__device__ __forceinline__ void renorm9(float a[9], float& ls) {
    float m = a[0];
    #pragma unroll
    for (int e = 1; e < 9; e++) m = fmaxf(m, a[e]);
    int eb = (__float_as_int(m) >> 23) - 127;
    float s = __int_as_float((127 - eb) << 23);   // exact 2^-eb
    #pragma unroll
    for (int e = 0; e < 9; e++) a[e] *= s;
    ls += (float)eb * LN2F;
}

__device__ __forceinline__ void mm3(const float a[9], const float b[9], float n[9]) {
    #pragma unroll
    for (int i = 0; i < 3; i++) {
        n[i*3+0] = fmaf(a[i*3], b[0], fmaf(a[i*3+1], b[3], a[i*3+2] * b[6]));
        n[i*3+1] = fmaf(a[i*3], b[1], fmaf(a[i*3+1], b[4], a[i*3+2] * b[7]));
        n[i*3+2] = fmaf(a[i*3], b[2], fmaf(a[i*3+1], b[5], a[i*3+2] * b[8]));
    }
}

__global__ __launch_bounds__(THREADS, 4) void fused_kernel(
    const float* __restrict__ x, const void* __restrict__ yraw,
    const float* __restrict__ W, const float* __restrict__ bias,
    const float* __restrict__ trans, const float* __restrict__ start_t,
    const float* __restrict__ stop_t, float* __restrict__ out,
    int nrows, int out_size)
{
    __shared__ float4 ws[3 * F4_PER_ROW];   // 9 KB
    __shared__ float bs[3];
    __shared__ float feats_sm[128 * 3];
    __shared__ float tr_sm[9], etr_sm[9], st_sm[3], sp_sm[3];
    __shared__ float wm[4][9], wls[4], wgold[4];
    __shared__ int s_flag;

    int tid  = threadIdx.x;
    int lane = tid & 31;
    int w    = tid >> 5;

    for (int i = tid; i < 3 * F4_PER_ROW; i += THREADS)
        ws[i] = reinterpret_cast<const float4*>(W)[i];
    if (tid < 9) { float t = trans[tid]; tr_sm[tid] = t; etr_sm[tid] = __expf(t); }
    if (tid < 3) { bs[tid] = bias[tid]; st_sm[tid] = start_t[tid]; sp_sm[tid] = stop_t[tid]; }
    __syncthreads();

    // ---------------- pred: 128 rows, chunk+quad software pipeline ----------------
    // All loads use immediate offsets off one per-warp base pointer; the next
    // chunk's (or next quad's chunk-0) 4 LDG.128 are always in flight.
    int gw = blockIdx.x * 8 + w;
    int wrow0 = gw * (QPW * RQ);
    const float4* xb = reinterpret_cast<const float4*>(x)
                       + (size_t)wrow0 * F4_PER_ROW + lane;

    float4 xv0, xv1, xv2, xv3;      // current chunk (4 rows)
    // prologue: quad 0, chunk 0
    xv0 = __ldcs(&xb[0 * F4_PER_ROW]);
    xv1 = __ldcs(&xb[1 * F4_PER_ROW]);
    xv2 = __ldcs(&xb[2 * F4_PER_ROW]);
    xv3 = __ldcs(&xb[3 * F4_PER_ROW]);

    #pragma unroll
    for (int q = 0; q < QPW; q++) {
        float a0x=0.f,a0y=0.f,a0z=0.f, a1x=0.f,a1y=0.f,a1z=0.f;
        float a2x=0.f,a2y=0.f,a2z=0.f, a3x=0.f,a3y=0.f,a3z=0.f;

        #pragma unroll
        for (int i = 0; i < CHUNKS; i++) {
            float4 xn0, xn1, xn2, xn3;
            if (i < CHUNKS - 1) {               // next chunk, same quad
                const int o = (i + 1) * 32;
                xn0 = __ldcs(&xb[0 * F4_PER_ROW + o]);
                xn1 = __ldcs(&xb[1 * F4_PER_ROW + o]);
                xn2 = __ldcs(&xb[2 * F4_PER_ROW + o]);
                xn3 = __ldcs(&xb[3 * F4_PER_ROW + o]);
            } else if (q < QPW - 1) {           // next quad, chunk 0 (covers epilogue)
                xn0 = __ldcs(&xb[QUAD_F4 + 0 * F4_PER_ROW]);
                xn1 = __ldcs(&xb[QUAD_F4 + 1 * F4_PER_ROW]);
                xn2 = __ldcs(&xb[QUAD_F4 + 2 * F4_PER_ROW]);
                xn3 = __ldcs(&xb[QUAD_F4 + 3 * F4_PER_ROW]);
            }
            float4 w0 = ws[i * 32 + lane];
            float4 w1 = ws[192 + i * 32 + lane];
            float4 w2 = ws[384 + i * 32 + lane];

            a0x = fmaf(xv0.x, w0.x, fmaf(xv0.y, w0.y, fmaf(xv0.z, w0.z, fmaf(xv0.w, w0.w, a0x))));
            a0y = fmaf(xv0.x, w1.x, fmaf(xv0.y, w1.y, fmaf(xv0.z, w1.z, fmaf(xv0.w, w1.w, a0y))));
            a0z = fmaf(xv0.x, w2.x, fmaf(xv0.y, w2.y, fmaf(xv0.z, w2.z, fmaf(xv0.w, w2.w, a0z))));
            a1x = fmaf(xv1.x, w0.x, fmaf(xv1.y, w0.y, fmaf(xv1.z, w0.z, fmaf(xv1.w, w0.w, a1x))));
            a1y = fmaf(xv1.x, w1.x, fmaf(xv1.y, w1.y, fmaf(xv1.z, w1.z, fmaf(xv1.w, w1.w, a1y))));
            a1z = fmaf(xv1.x, w2.x, fmaf(xv1.y, w2.y, fmaf(xv1.z, w2.z, fmaf(xv1.w, w2.w, a1z))));
            a2x = fmaf(xv2.x, w0.x, fmaf(xv2.y, w0.y, fmaf(xv2.z, w0.z, fmaf(xv2.w, w0.w, a2x))));
            a2y = fmaf(xv2.x, w1.x, fmaf(xv2.y, w1.y, fmaf(xv2.z, w1.z, fmaf(xv2.w, w1.w, a2y))));
            a2z = fmaf(xv2.x, w2.x, fmaf(xv2.y, w2.y, fmaf(xv2.z, w2.z, fmaf(xv2.w, w2.w, a2z))));
            a3x = fmaf(xv3.x, w0.x, fmaf(xv3.y, w0.y, fmaf(xv3.z, w0.z, fmaf(xv3.w, w0.w, a3x))));
            a3y = fmaf(xv3.x, w1.x, fmaf(xv3.y, w1.y, fmaf(xv3.z, w1.z, fmaf(xv3.w, w1.w, a3y))));
            a3z = fmaf(xv3.x, w2.x, fmaf(xv3.y, w2.y, fmaf(xv3.z, w2.z, fmaf(xv3.w, w2.w, a3z))));

            xv0 = xn0; xv1 = xn1; xv2 = xn2; xv3 = xn3;   // renamed, not copied
        }

        // butterfly reduce 12 sums; next quad's chunk-0 loads are in flight here
        #pragma unroll
        for (int off = 16; off; off >>= 1) {
            a0x += __shfl_xor_sync(FULLM, a0x, off); a0y += __shfl_xor_sync(FULLM, a0y, off);
            a0z += __shfl_xor_sync(FULLM, a0z, off); a1x += __shfl_xor_sync(FULLM, a1x, off);
            a1y += __shfl_xor_sync(FULLM, a1y, off); a1z += __shfl_xor_sync(FULLM, a1z, off);
            a2x += __shfl_xor_sync(FULLM, a2x, off); a2y += __shfl_xor_sync(FULLM, a2y, off);
            a2z += __shfl_xor_sync(FULLM, a2z, off); a3x += __shfl_xor_sync(FULLM, a3x, off);
            a3y += __shfl_xor_sync(FULLM, a3y, off); a3z += __shfl_xor_sync(FULLM, a3z, off);
        }
        if (lane < RQ) {
            float v0 = (lane == 0 ? a0x : lane == 1 ? a1x : lane == 2 ? a2x : a3x) + bs[0];
            float v1 = (lane == 0 ? a0y : lane == 1 ? a1y : lane == 2 ? a2y : a3y) + bs[1];
            float v2 = (lane == 0 ? a0z : lane == 1 ? a1z : lane == 2 ? a2z : a3z) + bs[2];
            int row = wrow0 + q * RQ + lane;
            float* o = out + (size_t)row * 3;
            o[0] = v0; o[1] = v1; o[2] = v2;
            int tl = w * 16 + q * 4 + lane;
            feats_sm[tl * 3 + 0] = v0;
            feats_sm[tl * 3 + 1] = v1;
            feats_sm[tl * 3 + 2] = v2;
        }
        xb += QUAD_F4;
    }
    __syncthreads();

    // ---------------- per-block CRF partial (unchanged from R11) ----------------
    int b       = blockIdx.x >> 2;
    int tb_base = (blockIdx.x & 3) * 128;

    if (w < 4) {
        int tl = w * 32 + lane;
        int tb = tb_base + tl;
        float f0 = feats_sm[tl*3], f1 = feats_sm[tl*3+1], f2 = feats_sm[tl*3+2];
        if (tb == 0) { f0 += st_sm[0]; f1 += st_sm[1]; f2 += st_sm[2]; }
        float c  = fmaxf(f0, fmaxf(f1, f2));
        float e0 = __expf(f0 - c), e1 = __expf(f1 - c), e2 = __expf(f2 - c);
        float a[9]; float ls = c;
        if (tb == 0) {
            a[0]=e0; a[1]=e1; a[2]=e2; a[3]=e0; a[4]=e1; a[5]=e2; a[6]=e0; a[7]=e1; a[8]=e2;
        } else {
            #pragma unroll
            for (int i = 0; i < 3; i++) {
                a[i*3+0] = etr_sm[i*3+0] * e0;
                a[i*3+1] = etr_sm[i*3+1] * e1;
                a[i*3+2] = etr_sm[i*3+2] * e2;
            }
        }
        #pragma unroll
        for (int off = 1; off < 32; off <<= 1) {
            float bm[9];
            #pragma unroll
            for (int e = 0; e < 9; e++) bm[e] = __shfl_down_sync(FULLM, a[e], off);
            float lsb = __shfl_down_sync(FULLM, ls, off);
            if ((lane & (2 * off - 1)) == 0) {
                float n[9];
                mm3(a, bm, n);
                #pragma unroll
                for (int e = 0; e < 9; e++) a[e] = n[e];
                ls += lsb;
                renorm9(a, ls);
            }
        }
        if (lane == 0) {
            #pragma unroll
            for (int e = 0; e < 9; e++) wm[w][e] = a[e];
            wls[w] = ls;
        }
    } else {
        int tl = (w - 4) * 32 + lane;
        int tb = tb_base + tl;
        const int* yw = (const int*)yraw;
        int oddw = (lane < 16) ? yw[2 * lane + 1] : 0;
        int stride = (__ballot_sync(FULLM, oddw != 0) == 0u) ? 2 : 1;
        const int* yb = yw + (size_t)b * S_LEN * stride;

        int tg = yb[tb * stride];
        float g = feats_sm[tl * 3 + tg];
        if (tb > 0) { int tp = yb[(tb - 1) * stride]; g += tr_sm[tp * 3 + tg]; }
        else         g += st_sm[tg];
        if (tb == S_LEN - 1) g += sp_sm[tg];
        #pragma unroll
        for (int off = 16; off; off >>= 1) g += __shfl_xor_sync(FULLM, g, off);
        if (lane == 0) wgold[w - 4] = g;
    }
    __syncthreads();

    if (tid == 0) {
        float p[9], n[9];
        #pragma unroll
        for (int e = 0; e < 9; e++) p[e] = wm[0][e];
        float ls = wls[0];
        #pragma unroll
        for (int j = 1; j < 4; j++) {
            mm3(p, wm[j], n);
            #pragma unroll
            for (int e = 0; e < 9; e++) p[e] = n[e];
            ls += wls[j];
            renorm9(p, ls);
        }
        #pragma unroll
        for (int e = 0; e < 9; e++) g_sm_[blockIdx.x][e] = p[e];
        g_sls[blockIdx.x] = ls;
        g_sg[blockIdx.x]  = wgold[0] + wgold[1] + wgold[2] + wgold[3];
        __threadfence();
        s_flag = (atomicAdd(&g_cnt[b], 1) == 3);
    }
    __syncthreads();
    if (!s_flag) return;

    if (tid == 0) {
        __threadfence();
        int base = b * 4;
        float p[9], n[9], q9[9];
        #pragma unroll
        for (int e = 0; e < 9; e++) p[e] = __ldcg(&g_sm_[base][e]);
        float ls   = __ldcg(&g_sls[base]);
        float gold = __ldcg(&g_sg[base]);
        #pragma unroll
        for (int j = 1; j < 4; j++) {
            #pragma unroll
            for (int e = 0; e < 9; e++) q9[e] = __ldcg(&g_sm_[base + j][e]);
            mm3(p, q9, n);
            #pragma unroll
            for (int e = 0; e < 9; e++) p[e] = n[e];
            ls += __ldcg(&g_sls[base + j]);
            renorm9(p, ls);
            gold += __ldcg(&g_sg[base + j]);
        }
        float z = p[0] * __expf(sp_sm[0]) + p[1] * __expf(sp_sm[1]) + p[2] * __expf(sp_sm[2]);
        g_part[b] = gold - (ls + __logf(z));
        g_cnt[b] = 0;
        __threadfence();
        s_flag = ((int)atomicAdd(&g_done, 1) == B_SZ - 1);
    }
    __syncthreads();

    if (s_flag && w == 0) {
        __threadfence();
        float s = __ldcg(&g_part[lane])      + __ldcg(&g_part[lane + 32])
                + __ldcg(&g_part[lane + 64]) + __ldcg(&g_part[lane + 96]);
        #pragma unroll
        for (int off = 16; off; off >>= 1) s += __shfl_xor_sync(FULLM, s, off);
        if (lane == 0) {
            out[out_size - 1] = -s / (float)B_SZ;
            g_done = 0;
        }
    }
}

// ---------------- launch ----------------
extern "C" void kernel_launch(void* const* d_in, const int* in_sizes, int n_in,
                              void* d_out, int out_size)
{
    const float* x     = (const float*)d_in[0];
    const void*  y     = d_in[1];
    const float* W     = (const float*)d_in[2];
    const float* bias  = (const float*)d_in[3];
    const float* trans = (const float*)d_in[4];
    const float* st    = (const float*)d_in[5];
    const float* sp    = (const float*)d_in[6];
    float* out = (float*)d_out;

    int nrows = in_sizes[0] / H_DIM;    // 65536

    fused_kernel<<<BLOCKS, THREADS>>>(x, y, W, bias, trans, st, sp,
                                      out, nrows, out_size);
}